// round 1
// baseline (speedup 1.0000x reference)
#include <cuda_runtime.h>
#include <cuda_bf16.h>

// Problem constants (fixed by the dataset)
#define BATCH      4096
#define NUM_CTX    10
#define NUM_NOISE  26
#define VEC_DIM    300
#define NUM_WORDS  100000

// Fused kernel: one CTA per batch row.
//   Phase 1: x[d] = D[doc[b], d] + sum_c W[ctx[b,c], d]   -> shared
//   Phase 2: 8 warps split the 26 noise targets; each warp does a
//            300-elem dot of x against column tgt of O (row-major 300x100000),
//            fully unrolled to 10 independent strided LDGs per lane for MLP.
__global__ __launch_bounds__(256) void dm_fused_kernel(
    const int*   __restrict__ ctx,   // (BATCH, NUM_CTX)
    const int*   __restrict__ doc,   // (BATCH,)
    const int*   __restrict__ tgt,   // (BATCH, NUM_NOISE)
    const float* __restrict__ D,     // (500000, 300)
    const float* __restrict__ W,     // (100000, 300)
    const float* __restrict__ O,     // (300, 100000)
    float*       __restrict__ out)   // (BATCH, NUM_NOISE)
{
    __shared__ float xs[VEC_DIM];
    __shared__ int   ctxs[NUM_CTX];
    __shared__ int   tgts[NUM_NOISE];
    __shared__ int   docid_sh;

    const int b   = blockIdx.x;
    const int tid = threadIdx.x;

    if (tid < NUM_CTX)   ctxs[tid] = ctx[b * NUM_CTX + tid];
    if (tid < NUM_NOISE) tgts[tid] = tgt[b * NUM_NOISE + tid];
    if (tid == 0)        docid_sh  = doc[b];
    __syncthreads();

    const int docid = docid_sh;

    // ---- Phase 1: build x[b] in shared (coalesced row reads) ----
    for (int d = tid; d < VEC_DIM; d += blockDim.x) {
        float v = __ldg(&D[(size_t)docid * VEC_DIM + d]);
        #pragma unroll
        for (int c = 0; c < NUM_CTX; c++) {
            v += __ldg(&W[(size_t)ctxs[c] * VEC_DIM + d]);
        }
        xs[d] = v;
    }
    __syncthreads();

    // ---- Phase 2: 26 dot products, warp-per-target ----
    const int warp  = tid >> 5;
    const int lane  = tid & 31;
    const int nwrp  = blockDim.x >> 5;   // 8

    for (int n = warp; n < NUM_NOISE; n += nwrp) {
        const int w = tgts[n];
        const float* __restrict__ Ocol = O + w;   // element (d, w) at d*NUM_WORDS
        float acc = 0.0f;

        // 300 = 9*32 + 12 : fully unroll for max memory-level parallelism.
        // The 9 full strides + 1 predicated tail issue as ~10 independent LDGs
        // per lane before the FMA chain binds.
        float ov[10];
        float xv[10];
        #pragma unroll
        for (int k = 0; k < 9; k++) {
            const int d = lane + 32 * k;
            ov[k] = __ldg(&Ocol[d * NUM_WORDS]);
            xv[k] = xs[d];
        }
        {
            const int d = lane + 288;
            if (lane < 12) {
                ov[9] = __ldg(&Ocol[d * NUM_WORDS]);
                xv[9] = xs[d];
            } else {
                ov[9] = 0.0f; xv[9] = 0.0f;
            }
        }
        #pragma unroll
        for (int k = 0; k < 10; k++) acc = fmaf(xv[k], ov[k], acc);

        // warp reduction
        #pragma unroll
        for (int off = 16; off > 0; off >>= 1)
            acc += __shfl_xor_sync(0xffffffffu, acc, off);

        if (lane == 0) out[b * NUM_NOISE + n] = acc;
    }
}

extern "C" void kernel_launch(void* const* d_in, const int* in_sizes, int n_in,
                              void* d_out, int out_size)
{
    const int*   ctx = (const int*)  d_in[0];   // context_ids
    const int*   doc = (const int*)  d_in[1];   // doc_ids
    const int*   tgt = (const int*)  d_in[2];   // target_noise_ids
    const float* D   = (const float*)d_in[3];   // D
    const float* W   = (const float*)d_in[4];   // W
    const float* O   = (const float*)d_in[5];   // O
    float*       out = (float*)d_out;

    dm_fused_kernel<<<BATCH, 256>>>(ctx, doc, tgt, D, W, O, out);
}

// round 2
// speedup vs baseline: 3.1430x; 3.1430x over previous
#include <cuda_runtime.h>
#include <cuda_bf16.h>

// Problem constants (fixed by the dataset)
#define BATCH      4096
#define NUM_CTX    10
#define NUM_NOISE  26
#define VEC_DIM    300
#define NUM_WORDS  100000

#define CHUNK_W    32                      // words per chunk (smem tile width)
#define NCHUNK     (NUM_WORDS / CHUNK_W)   // 3125 (exact)
#define CAP        192                     // bucket capacity (Poisson mean 34.1)

// -------- device scratch (allocation-free) --------
__device__ float    g_X[BATCH * VEC_DIM];          // 4.9 MB
__device__ int      g_cnt[NCHUNK];                 // per-chunk target count
__device__ unsigned g_bucket[NCHUNK * CAP];        // 2.4 MB packed (b,n,w_local)

// -------- K1: zero the per-chunk counters --------
__global__ void k_zero(void)
{
    int i = blockIdx.x * blockDim.x + threadIdx.x;
    if (i < NCHUNK) g_cnt[i] = 0;
}

// -------- K2: build X[b] = D[doc[b]] + sum_c W[ctx[b,c]] --------
__global__ __launch_bounds__(128) void k_build_x(
    const int*   __restrict__ ctx,
    const int*   __restrict__ doc,
    const float* __restrict__ D,
    const float* __restrict__ W)
{
    __shared__ int ctxs[NUM_CTX];
    __shared__ int docid_sh;

    const int b   = blockIdx.x;
    const int tid = threadIdx.x;

    if (tid < NUM_CTX) ctxs[tid] = ctx[b * NUM_CTX + tid];
    if (tid == 0)      docid_sh  = doc[b];
    __syncthreads();

    const int docid = docid_sh;
    for (int d = tid; d < VEC_DIM; d += 128) {
        float v = __ldg(&D[(size_t)docid * VEC_DIM + d]);
        #pragma unroll
        for (int c = 0; c < NUM_CTX; c++)
            v += __ldg(&W[(size_t)ctxs[c] * VEC_DIM + d]);
        g_X[b * VEC_DIM + d] = v;
    }
}

// -------- K3: scatter targets into chunk buckets --------
__global__ void k_scatter(const int* __restrict__ tgt)
{
    int i = blockIdx.x * blockDim.x + threadIdx.x;
    if (i >= BATCH * NUM_NOISE) return;
    const int b = i / NUM_NOISE;
    const int n = i - b * NUM_NOISE;
    const int w = tgt[i];
    const int c = w >> 5;                  // chunk id
    const int pos = atomicAdd(&g_cnt[c], 1);
    if (pos < CAP)
        g_bucket[c * CAP + pos] =
            ((unsigned)b << 10) | ((unsigned)n << 5) | (unsigned)(w & 31);
}

// -------- K4: stream O once; dot targets against shared tile --------
__global__ __launch_bounds__(256) void k_main(
    const float* __restrict__ O,     // (300, 100000) row-major
    float*       __restrict__ out)   // (4096, 26)
{
    __shared__ float sO[CHUNK_W][VEC_DIM + 1];   // pad: 301 (coprime to 32)

    const int c    = blockIdx.x;
    const int base = c * CHUNK_W;
    const int tid  = threadIdx.x;

    // Load O[0:300, base:base+32] coalesced: consecutive tid -> consecutive w.
    for (int i = tid; i < VEC_DIM * CHUNK_W; i += 256) {
        const int d = i >> 5;
        const int w = i & 31;
        sO[w][d] = __ldg(&O[(size_t)d * NUM_WORDS + base + w]);
    }
    __syncthreads();

    const int nt   = min(g_cnt[c], CAP);
    const int warp = tid >> 5;
    const int lane = tid & 31;

    for (int t = warp; t < nt; t += 8) {
        const unsigned e = g_bucket[c * CAP + t];
        const int w = e & 31;
        const int n = (e >> 5) & 31;
        const int b = e >> 10;

        const float* __restrict__ x = g_X + (size_t)b * VEC_DIM;
        float acc = 0.0f;

        // 300 = 9*32 + 12; x reads are coalesced (L2-hot), sO conflict-free.
        float xv[10], ov[10];
        #pragma unroll
        for (int k = 0; k < 9; k++) {
            const int d = lane + 32 * k;
            xv[k] = __ldg(&x[d]);
            ov[k] = sO[w][d];
        }
        if (lane < 12) {
            const int d = lane + 288;
            xv[9] = __ldg(&x[d]);
            ov[9] = sO[w][d];
        } else { xv[9] = 0.0f; ov[9] = 0.0f; }

        #pragma unroll
        for (int k = 0; k < 10; k++) acc = fmaf(xv[k], ov[k], acc);

        #pragma unroll
        for (int off = 16; off > 0; off >>= 1)
            acc += __shfl_xor_sync(0xffffffffu, acc, off);

        if (lane == 0) out[b * NUM_NOISE + n] = acc;
    }
}

extern "C" void kernel_launch(void* const* d_in, const int* in_sizes, int n_in,
                              void* d_out, int out_size)
{
    const int*   ctx = (const int*)  d_in[0];
    const int*   doc = (const int*)  d_in[1];
    const int*   tgt = (const int*)  d_in[2];
    const float* D   = (const float*)d_in[3];
    const float* W   = (const float*)d_in[4];
    const float* O   = (const float*)d_in[5];
    float*       out = (float*)d_out;

    k_zero<<<(NCHUNK + 255) / 256, 256>>>();
    k_build_x<<<BATCH, 128>>>(ctx, doc, D, W);
    k_scatter<<<(BATCH * NUM_NOISE + 255) / 256, 256>>>(tgt);
    k_main<<<NCHUNK, 256>>>(O, out);
}

// round 5
// speedup vs baseline: 3.8544x; 1.2263x over previous
#include <cuda_runtime.h>
#include <cuda_bf16.h>

// Problem constants (fixed by the dataset)
#define BATCH      4096
#define NUM_CTX    10
#define NUM_NOISE  26
#define VEC_DIM    300
#define NUM_WORDS  100000

#define CHUNK_W    32                      // words per chunk (smem tile width)
#define NCHUNK     (NUM_WORDS / CHUNK_W)   // 3125 (exact)
#define CAP        192                     // bucket capacity (Poisson mean 34.1)

#define BX_BLOCKS  (BATCH / 8)             // 512: 8 warps (rows) per block
#define ZERO_BLKS  ((NCHUNK + 255) / 256)  // 13

// -------- device scratch (allocation-free) --------
__device__ float    g_X[BATCH * VEC_DIM];          // 4.9 MB
__device__ int      g_cnt[NCHUNK];
__device__ unsigned g_bucket[NCHUNK * CAP];        // packed (b,n,w_local)

// -------- K1: build X (warp-per-row, float4) + zero counters --------
__global__ __launch_bounds__(256) void k_build_zero_x(
    const int*   __restrict__ ctx,
    const int*   __restrict__ doc,
    const float* __restrict__ D,
    const float* __restrict__ W)
{
    const int blk = blockIdx.x;
    if (blk >= BX_BLOCKS) {                 // tail blocks: zero chunk counters
        const int i = (blk - BX_BLOCKS) * 256 + threadIdx.x;
        if (i < NCHUNK) g_cnt[i] = 0;
        return;
    }

    const int warp = threadIdx.x >> 5;
    const int lane = threadIdx.x & 31;
    const int b    = blk * 8 + warp;

    const int docid = __ldg(&doc[b]);

    // 300 floats = 75 float4 per row: lane, lane+32, lane+64(<75 -> lane<11)
    const float4* __restrict__ Dr = (const float4*)(D + (size_t)docid * VEC_DIM);
    float4 a0 = __ldg(&Dr[lane]);
    float4 a1 = __ldg(&Dr[lane + 32]);
    float4 a2 = (lane < 11) ? __ldg(&Dr[lane + 64]) : make_float4(0,0,0,0);

    #pragma unroll
    for (int c = 0; c < NUM_CTX; c++) {
        const int w = __ldg(&ctx[b * NUM_CTX + c]);
        const float4* __restrict__ Wr = (const float4*)(W + (size_t)w * VEC_DIM);
        float4 v0 = __ldg(&Wr[lane]);
        float4 v1 = __ldg(&Wr[lane + 32]);
        a0.x += v0.x; a0.y += v0.y; a0.z += v0.z; a0.w += v0.w;
        a1.x += v1.x; a1.y += v1.y; a1.z += v1.z; a1.w += v1.w;
        if (lane < 11) {
            float4 v2 = __ldg(&Wr[lane + 64]);
            a2.x += v2.x; a2.y += v2.y; a2.z += v2.z; a2.w += v2.w;
        }
    }

    float4* __restrict__ X = (float4*)(g_X + (size_t)b * VEC_DIM);
    X[lane]      = a0;
    X[lane + 32] = a1;
    if (lane < 11) X[lane + 64] = a2;
}

// -------- K2: scatter targets into chunk buckets --------
__global__ void k_scatter(const int* __restrict__ tgt)
{
    int i = blockIdx.x * blockDim.x + threadIdx.x;
    if (i >= BATCH * NUM_NOISE) return;
    const int b = i / NUM_NOISE;
    const int n = i - b * NUM_NOISE;
    const int w = __ldg(&tgt[i]);
    const int c = w >> 5;
    const int pos = atomicAdd(&g_cnt[c], 1);
    if (pos < CAP)
        g_bucket[c * CAP + pos] =
            ((unsigned)b << 10) | ((unsigned)n << 5) | (unsigned)(w & 31);
}

// -------- K3: stream O once; dot targets against shared tile --------
__global__ __launch_bounds__(512) void k_main(
    const float* __restrict__ O,     // (300, 100000) row-major
    float*       __restrict__ out)   // (4096, 26)
{
    __shared__ float sO[CHUNK_W][VEC_DIM + 1];   // stride 301 (13 mod 32)

    const int c    = blockIdx.x;
    const int base = c * CHUNK_W;
    const int tid  = threadIdx.x;

    // Tile load: 2400 float4, 512 threads -> 5 rounds of LDG.128 + 4x STS.
    // Global: d-row segments of 128B, fully coalesced.
    // STS banks: (20*(t%8) + 13j + d0 + t/8) mod 32 -> all distinct per j.
    for (int i = tid; i < (VEC_DIM * CHUNK_W) / 4; i += 512) {
        const int d  = i >> 3;            // 8 float4 per d-row
        const int w4 = (i & 7) << 2;      // starting w of this float4
        float4 v = __ldg((const float4*)(O + (size_t)d * NUM_WORDS + base + w4));
        sO[w4 + 0][d] = v.x;
        sO[w4 + 1][d] = v.y;
        sO[w4 + 2][d] = v.z;
        sO[w4 + 3][d] = v.w;
    }
    __syncthreads();

    const int nt   = min(g_cnt[c], CAP);
    const int warp = tid >> 5;
    const int lane = tid & 31;

    for (int t = warp; t < nt; t += 16) {
        const unsigned e = g_bucket[c * CAP + t];
        const int w = e & 31;
        const int n = (e >> 5) & 31;
        const int b = e >> 10;

        const float* __restrict__ x = g_X + (size_t)b * VEC_DIM;
        float acc = 0.0f;

        // 300 = 9*32 + 12; x reads coalesced (L2-hot), sO conflict-free.
        float xv[10], ov[10];
        #pragma unroll
        for (int k = 0; k < 9; k++) {
            const int d = lane + 32 * k;
            xv[k] = __ldg(&x[d]);
            ov[k] = sO[w][d];
        }
        if (lane < 12) {
            const int d = lane + 288;
            xv[9] = __ldg(&x[d]);
            ov[9] = sO[w][d];
        } else { xv[9] = 0.0f; ov[9] = 0.0f; }

        #pragma unroll
        for (int k = 0; k < 10; k++) acc = fmaf(xv[k], ov[k], acc);

        #pragma unroll
        for (int off = 16; off > 0; off >>= 1)
            acc += __shfl_xor_sync(0xffffffffu, acc, off);

        if (lane == 0) out[b * NUM_NOISE + n] = acc;
    }
}

extern "C" void kernel_launch(void* const* d_in, const int* in_sizes, int n_in,
                              void* d_out, int out_size)
{
    const int*   ctx = (const int*)  d_in[0];
    const int*   doc = (const int*)  d_in[1];
    const int*   tgt = (const int*)  d_in[2];
    const float* D   = (const float*)d_in[3];
    const float* W   = (const float*)d_in[4];
    const float* O   = (const float*)d_in[5];
    float*       out = (float*)d_out;

    k_build_zero_x<<<BX_BLOCKS + ZERO_BLKS, 256>>>(ctx, doc, D, W);
    k_scatter<<<(BATCH * NUM_NOISE + 255) / 256, 256>>>(tgt);
    k_main<<<NCHUNK, 512>>>(O, out);
}

// round 7
// speedup vs baseline: 3.9856x; 1.0340x over previous
#include <cuda_runtime.h>
#include <cuda_bf16.h>

// Problem constants (fixed by the dataset)
#define BATCH      4096
#define NUM_CTX    10
#define NUM_NOISE  26
#define VEC_DIM    300
#define NUM_WORDS  100000

#define CHUNK_W    32                      // words per chunk (smem tile width)
#define NCHUNK     (NUM_WORDS / CHUNK_W)   // 3125 (exact)
#define CAP        192                     // bucket capacity (Poisson mean 34.1)

#define BX_BLOCKS  (BATCH / 4)             // 1024: 4 rows/block, 2 warps/row
#define ZERO_BLKS  ((NCHUNK + 255) / 256)  // 13

// -------- device scratch (allocation-free) --------
__device__ float    g_X[BATCH * VEC_DIM];          // 4.9 MB
__device__ int      g_cnt[NCHUNK];
__device__ unsigned g_bucket[NCHUNK * CAP];        // packed (b,n,w_local)

// -------- K1: build X (2 warps per row, float4, hoisted ids) + zero counters --------
__global__ __launch_bounds__(256) void k_build_zero_x(
    const int*   __restrict__ ctx,
    const int*   __restrict__ doc,
    const float* __restrict__ D,
    const float* __restrict__ W)
{
    const int blk = blockIdx.x;
    if (blk >= BX_BLOCKS) {                 // tail blocks: zero chunk counters
        const int i = (blk - BX_BLOCKS) * 256 + threadIdx.x;
        if (i < NCHUNK) g_cnt[i] = 0;
        return;
    }

    const int warp = threadIdx.x >> 5;      // 0..7
    const int lane = threadIdx.x & 31;
    const int b    = blk * 4 + (warp >> 1); // 4 rows per block
    const int h    = warp & 1;              // half: 0 -> f4[0..38), 1 -> f4[38..75)

    // Hoist ALL indices first: 11 independent small loads, no chains.
    const int docid = __ldg(&doc[b]);
    int wid[NUM_CTX];
    #pragma unroll
    for (int c = 0; c < NUM_CTX; c++) wid[c] = __ldg(&ctx[b * NUM_CTX + c]);

    // float4 index split: h=0 covers jA=lane (0..31) + jB=lane+32 (lane<6)
    //                     h=1 covers jA=lane+38 (38..69) + jB=lane+70 (lane<5)
    const int  base  = 38 * h;
    const int  jA    = base + lane;
    const int  jB    = base + 32 + lane;
    const bool predB = (32 + lane) < (h ? 37 : 38);

    const float4* __restrict__ Dr = (const float4*)(D + (size_t)docid * VEC_DIM);
    float4 aA = __ldg(&Dr[jA]);
    float4 aB = predB ? __ldg(&Dr[jB]) : make_float4(0, 0, 0, 0);

    #pragma unroll
    for (int c = 0; c < NUM_CTX; c++) {
        const float4* __restrict__ Wr = (const float4*)(W + (size_t)wid[c] * VEC_DIM);
        float4 vA = __ldg(&Wr[jA]);
        aA.x += vA.x; aA.y += vA.y; aA.z += vA.z; aA.w += vA.w;
        if (predB) {
            float4 vB = __ldg(&Wr[jB]);
            aB.x += vB.x; aB.y += vB.y; aB.z += vB.z; aB.w += vB.w;
        }
    }

    float4* __restrict__ X = (float4*)(g_X + (size_t)b * VEC_DIM);
    X[jA] = aA;
    if (predB) X[jB] = aB;
}

// -------- K2: scatter targets into chunk buckets --------
__global__ void k_scatter(const int* __restrict__ tgt)
{
    int i = blockIdx.x * blockDim.x + threadIdx.x;
    if (i >= BATCH * NUM_NOISE) return;
    const int b = i / NUM_NOISE;
    const int n = i - b * NUM_NOISE;
    const int w = __ldg(&tgt[i]);
    const int c = w >> 5;
    const int pos = atomicAdd(&g_cnt[c], 1);
    if (pos < CAP)
        g_bucket[c * CAP + pos] =
            ((unsigned)b << 10) | ((unsigned)n << 5) | (unsigned)(w & 31);
}

// -------- K3: stream O once; dot targets against shared tile --------
__device__ __forceinline__ void dot_one(
    unsigned e, const float (*sO)[VEC_DIM + 1], float* __restrict__ out, int lane)
{
    const int w = e & 31;
    const int n = (e >> 5) & 31;
    const int b = e >> 10;

    const float* __restrict__ x = g_X + (size_t)b * VEC_DIM;
    float acc = 0.0f;

    float xv[10], ov[10];
    #pragma unroll
    for (int k = 0; k < 9; k++) {
        const int d = lane + 32 * k;
        xv[k] = __ldg(&x[d]);
        ov[k] = sO[w][d];
    }
    if (lane < 12) {
        const int d = lane + 288;
        xv[9] = __ldg(&x[d]);
        ov[9] = sO[w][d];
    } else { xv[9] = 0.0f; ov[9] = 0.0f; }

    #pragma unroll
    for (int k = 0; k < 10; k++) acc = fmaf(xv[k], ov[k], acc);

    #pragma unroll
    for (int off = 16; off > 0; off >>= 1)
        acc += __shfl_xor_sync(0xffffffffu, acc, off);

    if (lane == 0) out[b * NUM_NOISE + n] = acc;
}

__global__ __launch_bounds__(512) void k_main(
    const float* __restrict__ O,     // (300, 100000) row-major
    float*       __restrict__ out)   // (4096, 26)
{
    __shared__ float sO[CHUNK_W][VEC_DIM + 1];   // stride 301 (13 mod 32)

    const int c    = blockIdx.x;
    const int base = c * CHUNK_W;
    const int tid  = threadIdx.x;
    const int warp = tid >> 5;
    const int lane = tid & 31;

    // Prefetch metadata + this warp's first 3 bucket entries BEFORE the tile
    // load, so the e -> b -> x dependency chain overlaps the LDG/STS stream.
    const int nt = min(__ldg(&g_cnt[c]), CAP);
    unsigned e0 = 0, e1 = 0, e2 = 0;
    if (warp < nt)      e0 = __ldg(&g_bucket[c * CAP + warp]);
    if (warp + 16 < nt) e1 = __ldg(&g_bucket[c * CAP + warp + 16]);
    if (warp + 32 < nt) e2 = __ldg(&g_bucket[c * CAP + warp + 32]);

    // Tile load: 2400 float4, 512 threads -> 5 rounds of LDG.128 + 4x STS.
    for (int i = tid; i < (VEC_DIM * CHUNK_W) / 4; i += 512) {
        const int d  = i >> 3;            // 8 float4 per d-row
        const int w4 = (i & 7) << 2;      // starting w of this float4
        float4 v = __ldg((const float4*)(O + (size_t)d * NUM_WORDS + base + w4));
        sO[w4 + 0][d] = v.x;
        sO[w4 + 1][d] = v.y;
        sO[w4 + 2][d] = v.z;
        sO[w4 + 3][d] = v.w;
    }
    __syncthreads();

    if (warp < nt)      dot_one(e0, sO, out, lane);
    if (warp + 16 < nt) dot_one(e1, sO, out, lane);
    if (warp + 32 < nt) dot_one(e2, sO, out, lane);
    for (int t = warp + 48; t < nt; t += 16)        // rare Poisson tail
        dot_one(__ldg(&g_bucket[c * CAP + t]), sO, out, lane);
}

extern "C" void kernel_launch(void* const* d_in, const int* in_sizes, int n_in,
                              void* d_out, int out_size)
{
    const int*   ctx = (const int*)  d_in[0];
    const int*   doc = (const int*)  d_in[1];
    const int*   tgt = (const int*)  d_in[2];
    const float* D   = (const float*)d_in[3];
    const float* W   = (const float*)d_in[4];
    const float* O   = (const float*)d_in[5];
    float*       out = (float*)d_out;

    k_build_zero_x<<<BX_BLOCKS + ZERO_BLKS, 256>>>(ctx, doc, D, W);
    k_scatter<<<(BATCH * NUM_NOISE + 255) / 256, 256>>>(tgt);
    k_main<<<NCHUNK, 512>>>(O, out);
}